// round 4
// baseline (speedup 1.0000x reference)
#include <cuda_runtime.h>

#define NN 50000
#define NP 50048
#define EE 800000
#define HH 128
#define GG 64
#define OUTC 8
#define SCAN_B 1024
#define SCAN_NB ((NN + SCAN_B - 1) / SCAN_B)   // 49

// ---- scratch (no allocs allowed) ----
__device__ __align__(16) float g_h[(size_t)NP * HH];   // h' = dinv * (in @ W)
__device__ __align__(16) float g_A[(size_t)NP * HH];   // layer outputs ping
__device__ __align__(16) float g_B[(size_t)NP * HH];   // layer outputs pong
__device__ int   g_deg[NP];
__device__ float g_dinv[NP];
__device__ int   g_rowptr[NP + 1];
__device__ int   g_cursor[NP];
__device__ int   g_csr[EE];
__device__ int   g_blocksum[SCAN_NB];
__device__ int   g_offG[GG + 1];
__device__ __align__(16) float g_pooled[GG * HH];

// ---------------- setup kernels ----------------

__global__ void k_zero() {
    int i = blockIdx.x * blockDim.x + threadIdx.x;
    if (i < NN) g_deg[i] = 0;
    if (i < GG * HH) g_pooled[i] = 0.0f;
}

// NOTE: edge_index / batch are int32 (JAX default x64-disabled demotes int64).
__global__ void k_deg(const int* __restrict__ ei) {
    int e = blockIdx.x * blockDim.x + threadIdx.x;
    if (e < EE) atomicAdd(&g_deg[ei[EE + e]], 1);
}

__global__ void k_dinv() {
    int i = blockIdx.x * blockDim.x + threadIdx.x;
    if (i < NN) g_dinv[i] = rsqrtf((float)g_deg[i] + 1.0f);
}

// batch is sorted: offG[g] = first index with batch[i] >= g (binary search)
__global__ void k_offG(const int* __restrict__ batch) {
    int g = threadIdx.x;
    if (g > GG) return;
    int lo = 0, hi = NN;
    while (lo < hi) {
        int mid = (lo + hi) >> 1;
        if (batch[mid] < g) lo = mid + 1; else hi = mid;
    }
    g_offG[g] = lo;
}

// ---- decoupled 3-stage scan: deg -> rowptr ----
__global__ void k_scan1() {
    __shared__ int warp_sums[32];
    int t = threadIdx.x, lane = t & 31, w = t >> 5;
    int i = blockIdx.x * SCAN_B + t;
    int v = (i < NN) ? g_deg[i] : 0;
    int s = v;
#pragma unroll
    for (int off = 1; off < 32; off <<= 1) {
        int n = __shfl_up_sync(0xffffffffu, s, off);
        if (lane >= off) s += n;
    }
    if (lane == 31) warp_sums[w] = s;
    __syncthreads();
    if (w == 0) {
        int ws = warp_sums[lane];
#pragma unroll
        for (int off = 1; off < 32; off <<= 1) {
            int n = __shfl_up_sync(0xffffffffu, ws, off);
            if (lane >= off) ws += n;
        }
        warp_sums[lane] = ws;
    }
    __syncthreads();
    int inc = s + (w > 0 ? warp_sums[w - 1] : 0);
    if (i < NN) g_rowptr[i + 1] = inc;   // block-local inclusive (partial)
    if (t == SCAN_B - 1) g_blocksum[blockIdx.x] = inc;
}

__global__ void k_scan2() {
    __shared__ int sh[SCAN_NB];
    int t = threadIdx.x;
    if (t < SCAN_NB) sh[t] = g_blocksum[t];
    __syncthreads();
    if (t == 0) {
        int run = 0;
        for (int b = 0; b < SCAN_NB; b++) { int v = sh[b]; sh[b] = run; run += v; }
    }
    __syncthreads();
    if (t < SCAN_NB) g_blocksum[t] = sh[t];
}

__global__ void k_scan3() {
    int i = blockIdx.x * SCAN_B + threadIdx.x;
    if (i < NN) {
        int off = g_blocksum[blockIdx.x];
        int inc = g_rowptr[i + 1] + off;
        g_rowptr[i + 1] = inc;
        g_cursor[i] = inc - g_deg[i];
    }
    if (i == 0) g_rowptr[0] = 0;
}

__global__ void k_fill(const int* __restrict__ ei) {
    int e = blockIdx.x * blockDim.x + threadIdx.x;
    if (e < EE) {
        int dst = ei[EE + e];
        int slot = atomicAdd(&g_cursor[dst], 1);
        g_csr[slot] = ei[e];
    }
}

// ---------------- GEMM: h' = dinv .* (X @ W)  ----------------
// 64 rows per block, 256 threads, each thread 4 rows x 8 cols, K tiled by 32.
__global__ void k_gemm(const float* __restrict__ Xext, const float* __restrict__ W, int inSel) {
    __shared__ float Ws[32][128];
    __shared__ float Xs[64][32];

    const float* X = (inSel == 0) ? Xext : (inSel == 1) ? g_A : g_B;

    int t  = threadIdx.x;          // 256
    int cq = t & 15;               // col group (8 cols each)
    int rg = t >> 4;               // row group (4 rows each)
    int row0 = blockIdx.x * 64;

    float acc[4][8];
#pragma unroll
    for (int j = 0; j < 4; j++)
#pragma unroll
        for (int c = 0; c < 8; c++) acc[j][c] = 0.0f;

    for (int k0 = 0; k0 < 128; k0 += 32) {
#pragma unroll
        for (int i = 0; i < 4; i++) {
            int idx = t * 16 + i * 4;      // 0..4095
            int kk = idx >> 7, j = idx & 127;
            *(float4*)&Ws[kk][j] = *(const float4*)&W[(size_t)(k0 + kk) * 128 + j];
        }
        {
            int tr = t >> 2, seg = t & 3;
            int row = row0 + tr;
            float4 a = make_float4(0.f, 0.f, 0.f, 0.f), b4 = a;
            if (row < NN) {
                const float* src = X + (size_t)row * 128 + k0 + seg * 8;
                a  = *(const float4*)src;
                b4 = *(const float4*)(src + 4);
            }
            *(float4*)&Xs[tr][seg * 8]     = a;
            *(float4*)&Xs[tr][seg * 8 + 4] = b4;
        }
        __syncthreads();

#pragma unroll
        for (int kk = 0; kk < 32; kk++) {
            float4 w0 = *(float4*)&Ws[kk][cq * 8];
            float4 w1 = *(float4*)&Ws[kk][cq * 8 + 4];
#pragma unroll
            for (int j = 0; j < 4; j++) {
                float xv = Xs[rg * 4 + j][kk];
                acc[j][0] += xv * w0.x; acc[j][1] += xv * w0.y;
                acc[j][2] += xv * w0.z; acc[j][3] += xv * w0.w;
                acc[j][4] += xv * w1.x; acc[j][5] += xv * w1.y;
                acc[j][6] += xv * w1.z; acc[j][7] += xv * w1.w;
            }
        }
        __syncthreads();
    }

#pragma unroll
    for (int j = 0; j < 4; j++) {
        int row = row0 + rg * 4 + j;
        if (row < NN) {
            float di = g_dinv[row];
            float4 o0 = make_float4(di * acc[j][0], di * acc[j][1], di * acc[j][2], di * acc[j][3]);
            float4 o1 = make_float4(di * acc[j][4], di * acc[j][5], di * acc[j][6], di * acc[j][7]);
            *(float4*)&g_h[(size_t)row * 128 + cq * 8]     = o0;
            *(float4*)&g_h[(size_t)row * 128 + cq * 8 + 4] = o1;
        }
    }
}

// ---------------- aggregation: warp per node, CSR gather ----------------
// out = dinv[i]*(sum_{src} h'[src] + h'[i]) + b ; optional relu
__global__ void k_agg(int outSel, const float* __restrict__ bias, int relu) {
    int warp = (int)((blockIdx.x * blockDim.x + threadIdx.x) >> 5);
    int lane = threadIdx.x & 31;
    if (warp >= NN) return;

    float* out = outSel ? g_B : g_A;

    int beg = g_rowptr[warp], end = g_rowptr[warp + 1];
    float4 s = make_float4(0.f, 0.f, 0.f, 0.f);

    int e = beg;
    for (; e + 4 <= end; e += 4) {
        int s0 = __ldg(&g_csr[e]);
        int s1 = __ldg(&g_csr[e + 1]);
        int s2 = __ldg(&g_csr[e + 2]);
        int s3 = __ldg(&g_csr[e + 3]);
        float4 v0 = __ldg((const float4*)&g_h[(size_t)s0 * 128 + lane * 4]);
        float4 v1 = __ldg((const float4*)&g_h[(size_t)s1 * 128 + lane * 4]);
        float4 v2 = __ldg((const float4*)&g_h[(size_t)s2 * 128 + lane * 4]);
        float4 v3 = __ldg((const float4*)&g_h[(size_t)s3 * 128 + lane * 4]);
        s.x += v0.x + v1.x + v2.x + v3.x;
        s.y += v0.y + v1.y + v2.y + v3.y;
        s.z += v0.z + v1.z + v2.z + v3.z;
        s.w += v0.w + v1.w + v2.w + v3.w;
    }
    for (; e < end; e++) {
        int src = __ldg(&g_csr[e]);
        float4 v = __ldg((const float4*)&g_h[(size_t)src * 128 + lane * 4]);
        s.x += v.x; s.y += v.y; s.z += v.z; s.w += v.w;
    }

    float4 hs = *(const float4*)&g_h[(size_t)warp * 128 + lane * 4];
    float di  = g_dinv[warp];
    float4 b4 = *(const float4*)&bias[lane * 4];
    float4 o;
    o.x = di * (s.x + hs.x) + b4.x;
    o.y = di * (s.y + hs.y) + b4.y;
    o.z = di * (s.z + hs.z) + b4.z;
    o.w = di * (s.w + hs.w) + b4.w;
    if (relu) {
        o.x = fmaxf(o.x, 0.f); o.y = fmaxf(o.y, 0.f);
        o.z = fmaxf(o.z, 0.f); o.w = fmaxf(o.w, 0.f);
    }
    *(float4*)&out[(size_t)warp * 128 + lane * 4] = o;
}

// ---------------- pooling (batch sorted -> contiguous ranges) ----------------
#define SPLITS 8
__global__ void k_pool() {
    int g  = blockIdx.y;
    int sp = blockIdx.x;
    int beg = g_offG[g];
    int cnt = g_offG[g + 1] - beg;
    if (cnt == 0) return;
    int per = (cnt + SPLITS - 1) / SPLITS;
    int s = sp * per;
    int e = min(cnt, s + per);
    if (s >= e) return;
    int c = threadIdx.x;
    float sum = 0.0f;
    for (int r = s; r < e; r++) sum += g_A[(size_t)(beg + r) * 128 + c];
    atomicAdd(&g_pooled[g * 128 + c], sum);
}

// ---------------- head ----------------
__global__ void k_head(const float* __restrict__ Wh, const float* __restrict__ bh,
                       float* __restrict__ out) {
    int t = threadIdx.x;       // 512
    int g = t >> 3, o = t & 7;
    int cnt = g_offG[g + 1] - g_offG[g];
    float scale = 1.0f / fmaxf((float)cnt, 1.0f);
    float acc = bh[o];
    for (int c = 0; c < 128; c++)
        acc += g_pooled[g * 128 + c] * scale * Wh[c * 8 + o];
    out[g * 8 + o] = acc;
}

// ---------------- launch ----------------
extern "C" void kernel_launch(void* const* d_in, const int* in_sizes, int n_in,
                              void* d_out, int out_size) {
    const float* x     = (const float*)d_in[0];
    const int*   ei    = (const int*)d_in[1];     // int32 (JAX x64 disabled)
    const int*   batch = (const int*)d_in[2];     // int32
    const float* W0 = (const float*)d_in[3];
    const float* b0 = (const float*)d_in[4];
    const float* W1 = (const float*)d_in[5];
    const float* b1 = (const float*)d_in[6];
    const float* W2 = (const float*)d_in[7];
    const float* b2 = (const float*)d_in[8];
    const float* Wh = (const float*)d_in[9];
    const float* bh = (const float*)d_in[10];
    float* out = (float*)d_out;

    // graph preprocessing
    k_zero<<<(NN + 255) / 256, 256>>>();
    k_deg <<<(EE + 255) / 256, 256>>>(ei);
    k_dinv<<<(NN + 255) / 256, 256>>>();
    k_offG<<<1, GG + 1>>>(batch);
    k_scan1<<<SCAN_NB, SCAN_B>>>();
    k_scan2<<<1, 64>>>();
    k_scan3<<<SCAN_NB, SCAN_B>>>();
    k_fill<<<(EE + 255) / 256, 256>>>(ei);

    int gemm_blocks = (NN + 63) / 64;
    int agg_blocks  = (NN + 7) / 8;   // 8 warps (nodes) per 256-thread block

    // layer 0: x -> g_A (relu)
    k_gemm<<<gemm_blocks, 256>>>(x, W0, 0);
    k_agg <<<agg_blocks, 256>>>(0, b0, 1);
    // layer 1: g_A -> g_B (relu)
    k_gemm<<<gemm_blocks, 256>>>(x, W1, 1);
    k_agg <<<agg_blocks, 256>>>(1, b1, 1);
    // layer 2: g_B -> g_A (no relu)
    k_gemm<<<gemm_blocks, 256>>>(x, W2, 2);
    k_agg <<<agg_blocks, 256>>>(0, b2, 0);

    // pooling + head
    dim3 pg(SPLITS, GG);
    k_pool<<<pg, 128>>>();
    k_head<<<1, 512>>>(Wh, bh, out);
}

// round 7
// speedup vs baseline: 1.2511x; 1.2511x over previous
#include <cuda_runtime.h>
#include <cuda_fp16.h>

#define NN 50000
#define NP 50048
#define EE 800000
#define HH 128
#define GG 64
#define SCAN_B 1024
#define SCAN_NB ((NN + SCAN_B - 1) / SCAN_B)   // 49

// ---- scratch (no allocs allowed) ----
__device__ __align__(16) __half g_h[(size_t)NP * HH];  // h' = dinv*(X@W), fp16
__device__ __align__(16) float  g_A[(size_t)NP * HH];  // activations ping (fp32)
__device__ __align__(16) float  g_B[(size_t)NP * HH];  // activations pong (fp32)
__device__ int   g_deg[NP];          // zero at module load; re-zeroed by k_scan3
__device__ float g_dinv[NP];
__device__ int   g_rowptr[NP + 1];
__device__ int   g_cursor[NP];
__device__ int   g_csr[EE];
__device__ int   g_blocksum[SCAN_NB];
__device__ int   g_offG[GG + 1];
__device__ __align__(16) float g_pooled[GG * HH];  // zero at load; re-zeroed by k_head

// ---------------- preprocessing ----------------

// edge_index / batch are int32 (JAX x64 disabled demotes int64).
__global__ void k_deg(const int* __restrict__ ei) {
    int e = blockIdx.x * blockDim.x + threadIdx.x;
    if (e < EE) atomicAdd(&g_deg[ei[EE + e]], 1);
}

__global__ void k_scan1() {
    __shared__ int warp_sums[32];
    int t = threadIdx.x, lane = t & 31, w = t >> 5;
    int i = blockIdx.x * SCAN_B + t;
    int v = (i < NN) ? g_deg[i] : 0;
    int s = v;
#pragma unroll
    for (int off = 1; off < 32; off <<= 1) {
        int n = __shfl_up_sync(0xffffffffu, s, off);
        if (lane >= off) s += n;
    }
    if (lane == 31) warp_sums[w] = s;
    __syncthreads();
    if (w == 0) {
        int ws = warp_sums[lane];
#pragma unroll
        for (int off = 1; off < 32; off <<= 1) {
            int n = __shfl_up_sync(0xffffffffu, ws, off);
            if (lane >= off) ws += n;
        }
        warp_sums[lane] = ws;
    }
    __syncthreads();
    int inc = s + (w > 0 ? warp_sums[w - 1] : 0);
    if (i < NN) g_rowptr[i + 1] = inc;
    if (t == SCAN_B - 1) g_blocksum[blockIdx.x] = inc;
}

__global__ void k_scan2() {
    __shared__ int sh[SCAN_NB];
    int t = threadIdx.x;
    if (t < SCAN_NB) sh[t] = g_blocksum[t];
    __syncthreads();
    if (t == 0) {
        int run = 0;
        for (int b = 0; b < SCAN_NB; b++) { int v = sh[b]; sh[b] = run; run += v; }
    }
    __syncthreads();
    if (t < SCAN_NB) g_blocksum[t] = sh[t];
}

// scan3 fused: finalize rowptr, seed cursor, compute dinv, re-zero deg for next run
__global__ void k_scan3() {
    int i = blockIdx.x * SCAN_B + threadIdx.x;
    if (i < NN) {
        int off = g_blocksum[blockIdx.x];
        int inc = g_rowptr[i + 1] + off;
        g_rowptr[i + 1] = inc;
        int d = g_deg[i];
        g_cursor[i] = inc - d;
        g_dinv[i] = rsqrtf((float)d + 1.0f);
        g_deg[i] = 0;                     // restore invariant for next launch
    }
    if (i == 0) g_rowptr[0] = 0;
}

__global__ void k_fill(const int* __restrict__ ei) {
    int e = blockIdx.x * blockDim.x + threadIdx.x;
    if (e < EE) {
        int dst = ei[EE + e];
        int slot = atomicAdd(&g_cursor[dst], 1);
        g_csr[slot] = ei[e];
    }
}

// batch sorted: offG[g] = lower_bound(batch, g)
__global__ void k_offG(const int* __restrict__ batch) {
    int g = threadIdx.x;
    if (g > GG) return;
    int lo = 0, hi = NN;
    while (lo < hi) {
        int mid = (lo + hi) >> 1;
        if (batch[mid] < g) lo = mid + 1; else hi = mid;
    }
    g_offG[g] = lo;
}

// ---------------- GEMM: g_h = half( dinv .* (X @ W) ) ----------------
// 128x128 tile, 256 threads, 8x8 per thread, packed f32x2 FMA (FFMA2).
// Xd holds the X chunk transposed AND duplicated: Xd[k][2r]=Xd[k][2r+1]=X[r][k],
// so the inner loop needs no packing movs: x-pairs and w-pairs both come in
// pre-packed via LDS.64.
__global__ void __launch_bounds__(256, 2) k_gemm(const float* __restrict__ Xext,
                                                 const float* __restrict__ W, int inSel) {
    __shared__ float Ws[32][128];
    __shared__ float Xd[32][256];

    const float* X = (inSel == 0) ? Xext : (inSel == 1) ? g_A : g_B;

    int t    = threadIdx.x;
    int cq   = t & 15;          // 16 col groups x 8 cols
    int rg   = t >> 4;          // 16 row groups x 8 rows
    int row0 = blockIdx.x * 128;
    int lrow = t & 127;
    int halfsel = t >> 7;       // 0/1 -> k-subrange

    unsigned long long acc[8][4];
#pragma unroll
    for (int j = 0; j < 8; j++)
#pragma unroll
        for (int c = 0; c < 4; c++) acc[j][c] = 0ull;

    for (int k0 = 0; k0 < 128; k0 += 32) {
        // load W chunk 32x128 (coalesced float4)
#pragma unroll
        for (int i = 0; i < 4; i++) {
            int idx = t * 16 + i * 4;
            int kk = idx >> 7, j = idx & 127;
            *(float4*)&Ws[kk][j] = *(const float4*)&W[(size_t)(k0 + kk) * 128 + j];
        }
        // load X chunk 128x32, transpose + duplicate into Xd
        {
            int grow = row0 + lrow;
#pragma unroll
            for (int s = 0; s < 4; s++) {
                int kb = halfsel * 16 + s * 4;
                float4 v = make_float4(0.f, 0.f, 0.f, 0.f);
                if (grow < NN)
                    v = *(const float4*)&X[(size_t)grow * 128 + k0 + kb];
                unsigned long long d0, d1, d2, d3;
                asm("mov.b64 %0, {%1, %1};" : "=l"(d0) : "r"(__float_as_uint(v.x)));
                asm("mov.b64 %0, {%1, %1};" : "=l"(d1) : "r"(__float_as_uint(v.y)));
                asm("mov.b64 %0, {%1, %1};" : "=l"(d2) : "r"(__float_as_uint(v.z)));
                asm("mov.b64 %0, {%1, %1};" : "=l"(d3) : "r"(__float_as_uint(v.w)));
                *(unsigned long long*)&Xd[kb + 0][2 * lrow] = d0;
                *(unsigned long long*)&Xd[kb + 1][2 * lrow] = d1;
                *(unsigned long long*)&Xd[kb + 2][2 * lrow] = d2;
                *(unsigned long long*)&Xd[kb + 3][2 * lrow] = d3;
            }
        }
        __syncthreads();

#pragma unroll
        for (int kk = 0; kk < 32; kk++) {
            unsigned long long wp0 = *(const unsigned long long*)&Ws[kk][cq * 8 + 0];
            unsigned long long wp1 = *(const unsigned long long*)&Ws[kk][cq * 8 + 2];
            unsigned long long wp2 = *(const unsigned long long*)&Ws[kk][cq * 8 + 4];
            unsigned long long wp3 = *(const unsigned long long*)&Ws[kk][cq * 8 + 6];
#pragma unroll
            for (int j = 0; j < 8; j++) {
                unsigned long long xp =
                    *(const unsigned long long*)&Xd[kk][2 * (rg * 8 + j)];
                asm("fma.rn.f32x2 %0, %1, %2, %0;" : "+l"(acc[j][0]) : "l"(xp), "l"(wp0));
                asm("fma.rn.f32x2 %0, %1, %2, %0;" : "+l"(acc[j][1]) : "l"(xp), "l"(wp1));
                asm("fma.rn.f32x2 %0, %1, %2, %0;" : "+l"(acc[j][2]) : "l"(xp), "l"(wp2));
                asm("fma.rn.f32x2 %0, %1, %2, %0;" : "+l"(acc[j][3]) : "l"(xp), "l"(wp3));
            }
        }
        __syncthreads();
    }

    // epilogue: scale by dinv, convert to half, store 8 halves (16B) per row
#pragma unroll
    for (int j = 0; j < 8; j++) {
        int row = row0 + rg * 8 + j;
        if (row < NN) {
            float di = g_dinv[row];
            union { unsigned long long u; float2 f; } c0, c1, c2, c3;
            c0.u = acc[j][0]; c1.u = acc[j][1]; c2.u = acc[j][2]; c3.u = acc[j][3];
            __half2 h0 = __floats2half2_rn(c0.f.x * di, c0.f.y * di);
            __half2 h1 = __floats2half2_rn(c1.f.x * di, c1.f.y * di);
            __half2 h2 = __floats2half2_rn(c2.f.x * di, c2.f.y * di);
            __half2 h3 = __floats2half2_rn(c3.f.x * di, c3.f.y * di);
            uint4 o;
            o.x = *(unsigned*)&h0; o.y = *(unsigned*)&h1;
            o.z = *(unsigned*)&h2; o.w = *(unsigned*)&h3;
            *(uint4*)&g_h[(size_t)row * 128 + cq * 8] = o;
        }
    }
}

// ---------------- aggregation: warp per node, fp16 CSR gather ----------------
__global__ void k_agg(int outSel, const float* __restrict__ bias, int relu) {
    int warp = (int)((blockIdx.x * blockDim.x + threadIdx.x) >> 5);
    int lane = threadIdx.x & 31;
    if (warp >= NN) return;

    float* out = outSel ? g_B : g_A;

    int beg = g_rowptr[warp], end = g_rowptr[warp + 1];
    float4 s = make_float4(0.f, 0.f, 0.f, 0.f);

    int e = beg;
    for (; e + 4 <= end; e += 4) {
        int s0 = __ldg(&g_csr[e]);
        int s1 = __ldg(&g_csr[e + 1]);
        int s2 = __ldg(&g_csr[e + 2]);
        int s3 = __ldg(&g_csr[e + 3]);
        uint2 u0 = __ldg((const uint2*)&g_h[(size_t)s0 * 128 + lane * 4]);
        uint2 u1 = __ldg((const uint2*)&g_h[(size_t)s1 * 128 + lane * 4]);
        uint2 u2 = __ldg((const uint2*)&g_h[(size_t)s2 * 128 + lane * 4]);
        uint2 u3 = __ldg((const uint2*)&g_h[(size_t)s3 * 128 + lane * 4]);
        float2 a, b;
        a = __half22float2(*(__half2*)&u0.x); b = __half22float2(*(__half2*)&u0.y);
        s.x += a.x; s.y += a.y; s.z += b.x; s.w += b.y;
        a = __half22float2(*(__half2*)&u1.x); b = __half22float2(*(__half2*)&u1.y);
        s.x += a.x; s.y += a.y; s.z += b.x; s.w += b.y;
        a = __half22float2(*(__half2*)&u2.x); b = __half22float2(*(__half2*)&u2.y);
        s.x += a.x; s.y += a.y; s.z += b.x; s.w += b.y;
        a = __half22float2(*(__half2*)&u3.x); b = __half22float2(*(__half2*)&u3.y);
        s.x += a.x; s.y += a.y; s.z += b.x; s.w += b.y;
    }
    for (; e < end; e++) {
        int src = __ldg(&g_csr[e]);
        uint2 u = __ldg((const uint2*)&g_h[(size_t)src * 128 + lane * 4]);
        float2 a = __half22float2(*(__half2*)&u.x);
        float2 b = __half22float2(*(__half2*)&u.y);
        s.x += a.x; s.y += a.y; s.z += b.x; s.w += b.y;
    }

    // self-loop term
    {
        uint2 u = *(const uint2*)&g_h[(size_t)warp * 128 + lane * 4];
        float2 a = __half22float2(*(__half2*)&u.x);
        float2 b = __half22float2(*(__half2*)&u.y);
        s.x += a.x; s.y += a.y; s.z += b.x; s.w += b.y;
    }
    float di  = g_dinv[warp];
    float4 b4 = *(const float4*)&bias[lane * 4];
    float4 o;
    o.x = di * s.x + b4.x;
    o.y = di * s.y + b4.y;
    o.z = di * s.z + b4.z;
    o.w = di * s.w + b4.w;
    if (relu) {
        o.x = fmaxf(o.x, 0.f); o.y = fmaxf(o.y, 0.f);
        o.z = fmaxf(o.z, 0.f); o.w = fmaxf(o.w, 0.f);
    }
    *(float4*)&out[(size_t)warp * 128 + lane * 4] = o;
}

// ---------------- pooling (batch sorted -> contiguous ranges) ----------------
#define SPLITS 8
__global__ void k_pool() {
    int g  = blockIdx.y;
    int sp = blockIdx.x;
    int beg = g_offG[g];
    int cnt = g_offG[g + 1] - beg;
    if (cnt == 0) return;
    int per = (cnt + SPLITS - 1) / SPLITS;
    int s = sp * per;
    int e = min(cnt, s + per);
    if (s >= e) return;
    int c = threadIdx.x;
    float sum = 0.0f;
    for (int r = s; r < e; r++) sum += g_A[(size_t)(beg + r) * 128 + c];
    atomicAdd(&g_pooled[g * 128 + c], sum);
}

// ---------------- head (also re-zeroes g_pooled for next run) ----------------
__global__ void k_head(const float* __restrict__ Wh, const float* __restrict__ bh,
                       float* __restrict__ out) {
    int t = threadIdx.x;       // 512
    int g = t >> 3, o = t & 7;
    int cnt = g_offG[g + 1] - g_offG[g];
    float scale = 1.0f / fmaxf((float)cnt, 1.0f);
    float acc = bh[o];
    for (int c = 0; c < 128; c++)
        acc += g_pooled[g * 128 + c] * scale * Wh[c * 8 + o];
    out[g * 8 + o] = acc;
    __syncthreads();
    for (int i = t; i < GG * HH; i += 512) g_pooled[i] = 0.0f;   // restore invariant
}

// ---------------- launch ----------------
extern "C" void kernel_launch(void* const* d_in, const int* in_sizes, int n_in,
                              void* d_out, int out_size) {
    const float* x     = (const float*)d_in[0];
    const int*   ei    = (const int*)d_in[1];
    const int*   batch = (const int*)d_in[2];
    const float* W0 = (const float*)d_in[3];
    const float* b0 = (const float*)d_in[4];
    const float* W1 = (const float*)d_in[5];
    const float* b1 = (const float*)d_in[6];
    const float* W2 = (const float*)d_in[7];
    const float* b2 = (const float*)d_in[8];
    const float* Wh = (const float*)d_in[9];
    const float* bh = (const float*)d_in[10];
    float* out = (float*)d_out;

    k_deg  <<<(EE + 255) / 256, 256>>>(ei);       // 1
    k_scan1<<<SCAN_NB, SCAN_B>>>();               // 2
    k_scan2<<<1, 64>>>();                         // 3
    k_scan3<<<SCAN_NB, SCAN_B>>>();               // 4 (dinv + cursor + zero deg)
    k_fill <<<(EE + 255) / 256, 256>>>(ei);       // 5

    int gemm_blocks = (NN + 127) / 128;
    int agg_blocks  = (NN + 7) / 8;

    k_gemm<<<gemm_blocks, 256>>>(x, W0, 0);       // 6  <- ncu capture target
    k_offG<<<1, GG + 1>>>(batch);                 // 7 (independent; before pool)
    k_agg <<<agg_blocks, 256>>>(0, b0, 1);        // 8
    k_gemm<<<gemm_blocks, 256>>>(x, W1, 1);       // 9
    k_agg <<<agg_blocks, 256>>>(1, b1, 1);        // 10
    k_gemm<<<gemm_blocks, 256>>>(x, W2, 2);       // 11
    k_agg <<<agg_blocks, 256>>>(0, b2, 0);        // 12

    dim3 pg(SPLITS, GG);
    k_pool<<<pg, 128>>>();                        // 13
    k_head<<<1, 512>>>(Wh, bh, out);              // 14
}

// round 12
// speedup vs baseline: 1.6603x; 1.3271x over previous
#include <cuda_runtime.h>
#include <cuda_fp16.h>

#define NN 50000
#define NP 50048
#define EE 800000
#define HH 128
#define GG 64
#define SCAN_B 1024
#define SCAN_NB ((NN + SCAN_B - 1) / SCAN_B)   // 49

// ---- scratch (no allocs allowed) ----
__device__ __align__(16) __half g_h[(size_t)NP * HH];  // h' = dinv*(X@W), fp16
__device__ __align__(16) float  g_A[(size_t)NP * HH];  // activations ping (fp32)
__device__ __align__(16) float  g_B[(size_t)NP * HH];  // activations pong (fp32)
__device__ int   g_deg[NP];          // zero at module load; re-zeroed by k_scan3
__device__ float g_dinv[NP];
__device__ int   g_rowptr[NP + 1];
__device__ int   g_cursor[NP];
__device__ int   g_csr[EE];
__device__ int   g_blocksum[SCAN_NB];
__device__ int   g_offG[GG + 1];
__device__ __align__(16) float g_pooled[GG * HH];  // zero at load; re-zeroed by k_head

// ---------------- preprocessing ----------------

// edge_index / batch are int32 (JAX x64 disabled demotes int64).
__global__ void k_deg(const int* __restrict__ ei) {
    int e = blockIdx.x * blockDim.x + threadIdx.x;
    if (e < EE) atomicAdd(&g_deg[ei[EE + e]], 1);
}

__global__ void k_scan1() {
    __shared__ int warp_sums[32];
    int t = threadIdx.x, lane = t & 31, w = t >> 5;
    int i = blockIdx.x * SCAN_B + t;
    int v = (i < NN) ? g_deg[i] : 0;
    int s = v;
#pragma unroll
    for (int off = 1; off < 32; off <<= 1) {
        int n = __shfl_up_sync(0xffffffffu, s, off);
        if (lane >= off) s += n;
    }
    if (lane == 31) warp_sums[w] = s;
    __syncthreads();
    if (w == 0) {
        int ws = warp_sums[lane];
#pragma unroll
        for (int off = 1; off < 32; off <<= 1) {
            int n = __shfl_up_sync(0xffffffffu, ws, off);
            if (lane >= off) ws += n;
        }
        warp_sums[lane] = ws;
    }
    __syncthreads();
    int inc = s + (w > 0 ? warp_sums[w - 1] : 0);
    if (i < NN) g_rowptr[i + 1] = inc;
    if (t == SCAN_B - 1) g_blocksum[blockIdx.x] = inc;
}

__global__ void k_scan2() {
    __shared__ int sh[SCAN_NB];
    int t = threadIdx.x;
    if (t < SCAN_NB) sh[t] = g_blocksum[t];
    __syncthreads();
    if (t == 0) {
        int run = 0;
        for (int b = 0; b < SCAN_NB; b++) { int v = sh[b]; sh[b] = run; run += v; }
    }
    __syncthreads();
    if (t < SCAN_NB) g_blocksum[t] = sh[t];
}

// scan3 fused: finalize rowptr, seed cursor, compute dinv, re-zero deg for next run
__global__ void k_scan3() {
    int i = blockIdx.x * SCAN_B + threadIdx.x;
    if (i < NN) {
        int off = g_blocksum[blockIdx.x];
        int inc = g_rowptr[i + 1] + off;
        g_rowptr[i + 1] = inc;
        int d = g_deg[i];
        g_cursor[i] = inc - d;
        g_dinv[i] = rsqrtf((float)d + 1.0f);
        g_deg[i] = 0;                     // restore invariant for next launch
    }
    if (i == 0) g_rowptr[0] = 0;
}

__global__ void k_fill(const int* __restrict__ ei) {
    int e = blockIdx.x * blockDim.x + threadIdx.x;
    if (e < EE) {
        int dst = ei[EE + e];
        int slot = atomicAdd(&g_cursor[dst], 1);
        g_csr[slot] = ei[e];
    }
}

// batch sorted: offG[g] = lower_bound(batch, g)
__global__ void k_offG(const int* __restrict__ batch) {
    int g = threadIdx.x;
    if (g > GG) return;
    int lo = 0, hi = NN;
    while (lo < hi) {
        int mid = (lo + hi) >> 1;
        if (batch[mid] < g) lo = mid + 1; else hi = mid;
    }
    g_offG[g] = lo;
}

// ---------------- GEMM: g_h = half( dinv .* (X @ W) ), tf32 tensor-core ----------------
// Block tile 128m x 128n, K chunked by 32. 8 warps; warp-tile 32m x 64n:
// warp w -> m-strip (w&3)*32, n-half (w>>2)*64. m16n8k8 tf32 mma.sync.
__device__ __forceinline__ unsigned f2tf32(float f) {
    unsigned r;
    asm("cvt.rna.tf32.f32 %0, %1;" : "=r"(r) : "f"(f));
    return r;
}

__global__ void __launch_bounds__(256, 2) k_gemm(const float* __restrict__ Xext,
                                                 const float* __restrict__ W, int inSel) {
    __shared__ unsigned Xs[128][33];   // tf32 bits, row-major, pad 33
    __shared__ unsigned Ws[32][132];   // tf32 bits, [k][n], pad 132

    const float* X = (inSel == 0) ? Xext : (inSel == 1) ? g_A : g_B;

    int t    = threadIdx.x;
    int lane = t & 31, w = t >> 5;
    int g    = lane >> 2;        // 0..7
    int tig  = lane & 3;         // 0..3
    int mbase = (w & 3) * 32;    // warp m offset in block
    int nhalf = (w >> 2) * 64;   // warp n offset in block
    int row0 = blockIdx.x * 128;

    float acc[2][8][4];
#pragma unroll
    for (int mt = 0; mt < 2; mt++)
#pragma unroll
        for (int nt = 0; nt < 8; nt++)
#pragma unroll
            for (int c = 0; c < 4; c++) acc[mt][nt][c] = 0.0f;

    for (int k0 = 0; k0 < 128; k0 += 32) {
        // fill Xs: 128 rows x 32 k; thread t: row=t>>1, k-base=(t&1)*16, 4 float4
        {
            int rr = t >> 1, kq = (t & 1) * 16;
            int grow = row0 + rr;
#pragma unroll
            for (int i = 0; i < 4; i++) {
                float4 v = make_float4(0.f, 0.f, 0.f, 0.f);
                if (grow < NN)
                    v = *(const float4*)&X[(size_t)grow * 128 + k0 + kq + i * 4];
                Xs[rr][kq + i * 4 + 0] = f2tf32(v.x);
                Xs[rr][kq + i * 4 + 1] = f2tf32(v.y);
                Xs[rr][kq + i * 4 + 2] = f2tf32(v.z);
                Xs[rr][kq + i * 4 + 3] = f2tf32(v.w);
            }
        }
        // fill Ws: 32 k x 128 n; thread t: k=t>>3, n-base=(t&7)*16, 4 float4
        {
            int kr = t >> 3, nq = (t & 7) * 16;
#pragma unroll
            for (int i = 0; i < 4; i++) {
                float4 v = *(const float4*)&W[(size_t)(k0 + kr) * 128 + nq + i * 4];
                Ws[kr][nq + i * 4 + 0] = f2tf32(v.x);
                Ws[kr][nq + i * 4 + 1] = f2tf32(v.y);
                Ws[kr][nq + i * 4 + 2] = f2tf32(v.z);
                Ws[kr][nq + i * 4 + 3] = f2tf32(v.w);
            }
        }
        __syncthreads();

#pragma unroll
        for (int ks = 0; ks < 4; ks++) {
            int kk = ks * 8;
            unsigned a[2][4];
#pragma unroll
            for (int mt = 0; mt < 2; mt++) {
                int r = mbase + mt * 16;
                a[mt][0] = Xs[r + g][kk + tig];
                a[mt][1] = Xs[r + g + 8][kk + tig];
                a[mt][2] = Xs[r + g][kk + tig + 4];
                a[mt][3] = Xs[r + g + 8][kk + tig + 4];
            }
#pragma unroll
            for (int nt = 0; nt < 8; nt++) {
                unsigned b0 = Ws[kk + tig][nhalf + nt * 8 + g];
                unsigned b1 = Ws[kk + tig + 4][nhalf + nt * 8 + g];
#pragma unroll
                for (int mt = 0; mt < 2; mt++) {
                    asm volatile(
                        "mma.sync.aligned.m16n8k8.row.col.f32.tf32.tf32.f32 "
                        "{%0,%1,%2,%3}, {%4,%5,%6,%7}, {%8,%9}, {%0,%1,%2,%3};"
                        : "+f"(acc[mt][nt][0]), "+f"(acc[mt][nt][1]),
                          "+f"(acc[mt][nt][2]), "+f"(acc[mt][nt][3])
                        : "r"(a[mt][0]), "r"(a[mt][1]), "r"(a[mt][2]), "r"(a[mt][3]),
                          "r"(b0), "r"(b1));
                }
            }
        }
        __syncthreads();
    }

    // epilogue: c0:(row g, col 2tig) c1:(g,2tig+1) c2:(g+8,2tig) c3:(g+8,2tig+1)
#pragma unroll
    for (int mt = 0; mt < 2; mt++) {
        int r0 = row0 + mbase + mt * 16 + g;
        int r1 = r0 + 8;
        float d0 = (r0 < NN) ? g_dinv[r0] : 0.0f;
        float d1 = (r1 < NN) ? g_dinv[r1] : 0.0f;
#pragma unroll
        for (int nt = 0; nt < 8; nt++) {
            int c = nhalf + nt * 8 + 2 * tig;
            if (r0 < NN) {
                __half2 h = __floats2half2_rn(acc[mt][nt][0] * d0, acc[mt][nt][1] * d0);
                *(__half2*)&g_h[(size_t)r0 * 128 + c] = h;
            }
            if (r1 < NN) {
                __half2 h = __floats2half2_rn(acc[mt][nt][2] * d1, acc[mt][nt][3] * d1);
                *(__half2*)&g_h[(size_t)r1 * 128 + c] = h;
            }
        }
    }
}

// ---------------- aggregation: warp per node, fp16 CSR gather ----------------
__global__ void k_agg(int outSel, const float* __restrict__ bias, int relu) {
    int warp = (int)((blockIdx.x * blockDim.x + threadIdx.x) >> 5);
    int lane = threadIdx.x & 31;
    if (warp >= NN) return;

    float* out = outSel ? g_B : g_A;

    int beg = g_rowptr[warp], end = g_rowptr[warp + 1];
    float4 s = make_float4(0.f, 0.f, 0.f, 0.f);

    int e = beg;
    for (; e + 4 <= end; e += 4) {
        int s0 = __ldg(&g_csr[e]);
        int s1 = __ldg(&g_csr[e + 1]);
        int s2 = __ldg(&g_csr[e + 2]);
        int s3 = __ldg(&g_csr[e + 3]);
        uint2 u0 = __ldg((const uint2*)&g_h[(size_t)s0 * 128 + lane * 4]);
        uint2 u1 = __ldg((const uint2*)&g_h[(size_t)s1 * 128 + lane * 4]);
        uint2 u2 = __ldg((const uint2*)&g_h[(size_t)s2 * 128 + lane * 4]);
        uint2 u3 = __ldg((const uint2*)&g_h[(size_t)s3 * 128 + lane * 4]);
        float2 a, b;
        a = __half22float2(*(__half2*)&u0.x); b = __half22float2(*(__half2*)&u0.y);
        s.x += a.x; s.y += a.y; s.z += b.x; s.w += b.y;
        a = __half22float2(*(__half2*)&u1.x); b = __half22float2(*(__half2*)&u1.y);
        s.x += a.x; s.y += a.y; s.z += b.x; s.w += b.y;
        a = __half22float2(*(__half2*)&u2.x); b = __half22float2(*(__half2*)&u2.y);
        s.x += a.x; s.y += a.y; s.z += b.x; s.w += b.y;
        a = __half22float2(*(__half2*)&u3.x); b = __half22float2(*(__half2*)&u3.y);
        s.x += a.x; s.y += a.y; s.z += b.x; s.w += b.y;
    }
    for (; e < end; e++) {
        int src = __ldg(&g_csr[e]);
        uint2 u = __ldg((const uint2*)&g_h[(size_t)src * 128 + lane * 4]);
        float2 a = __half22float2(*(__half2*)&u.x);
        float2 b = __half22float2(*(__half2*)&u.y);
        s.x += a.x; s.y += a.y; s.z += b.x; s.w += b.y;
    }

    // self-loop term
    {
        uint2 u = *(const uint2*)&g_h[(size_t)warp * 128 + lane * 4];
        float2 a = __half22float2(*(__half2*)&u.x);
        float2 b = __half22float2(*(__half2*)&u.y);
        s.x += a.x; s.y += a.y; s.z += b.x; s.w += b.y;
    }
    float di  = g_dinv[warp];
    float4 b4 = *(const float4*)&bias[lane * 4];
    float4 o;
    o.x = di * s.x + b4.x;
    o.y = di * s.y + b4.y;
    o.z = di * s.z + b4.z;
    o.w = di * s.w + b4.w;
    if (relu) {
        o.x = fmaxf(o.x, 0.f); o.y = fmaxf(o.y, 0.f);
        o.z = fmaxf(o.z, 0.f); o.w = fmaxf(o.w, 0.f);
    }
    *(float4*)&out[(size_t)warp * 128 + lane * 4] = o;
}

// ---------------- pooling (batch sorted -> contiguous ranges) ----------------
#define SPLITS 8
__global__ void k_pool() {
    int g  = blockIdx.y;
    int sp = blockIdx.x;
    int beg = g_offG[g];
    int cnt = g_offG[g + 1] - beg;
    if (cnt == 0) return;
    int per = (cnt + SPLITS - 1) / SPLITS;
    int s = sp * per;
    int e = min(cnt, s + per);
    if (s >= e) return;
    int c = threadIdx.x;
    float sum = 0.0f;
    for (int r = s; r < e; r++) sum += g_A[(size_t)(beg + r) * 128 + c];
    atomicAdd(&g_pooled[g * 128 + c], sum);
}

// ---------------- head (also re-zeroes g_pooled for next run) ----------------
__global__ void k_head(const float* __restrict__ Wh, const float* __restrict__ bh,
                       float* __restrict__ out) {
    int t = threadIdx.x;       // 512
    int g = t >> 3, o = t & 7;
    int cnt = g_offG[g + 1] - g_offG[g];
    float scale = 1.0f / fmaxf((float)cnt, 1.0f);
    float acc = bh[o];
    for (int c = 0; c < 128; c++)
        acc += g_pooled[g * 128 + c] * scale * Wh[c * 8 + o];
    out[g * 8 + o] = acc;
    __syncthreads();
    for (int i = t; i < GG * HH; i += 512) g_pooled[i] = 0.0f;   // restore invariant
}

// ---------------- launch ----------------
extern "C" void kernel_launch(void* const* d_in, const int* in_sizes, int n_in,
                              void* d_out, int out_size) {
    const float* x     = (const float*)d_in[0];
    const int*   ei    = (const int*)d_in[1];
    const int*   batch = (const int*)d_in[2];
    const float* W0 = (const float*)d_in[3];
    const float* b0 = (const float*)d_in[4];
    const float* W1 = (const float*)d_in[5];
    const float* b1 = (const float*)d_in[6];
    const float* W2 = (const float*)d_in[7];
    const float* b2 = (const float*)d_in[8];
    const float* Wh = (const float*)d_in[9];
    const float* bh = (const float*)d_in[10];
    float* out = (float*)d_out;

    k_deg  <<<(EE + 255) / 256, 256>>>(ei);       // 1
    k_scan1<<<SCAN_NB, SCAN_B>>>();               // 2
    k_scan2<<<1, 64>>>();                         // 3
    k_scan3<<<SCAN_NB, SCAN_B>>>();               // 4 (dinv + cursor + zero deg)
    k_fill <<<(EE + 255) / 256, 256>>>(ei);       // 5

    int gemm_blocks = (NN + 127) / 128;
    int agg_blocks  = (NN + 7) / 8;

    k_gemm<<<gemm_blocks, 256>>>(x, W0, 0);       // 6  <- ncu capture target
    k_offG<<<1, GG + 1>>>(batch);                 // 7 (independent; before pool)
    k_agg <<<agg_blocks, 256>>>(0, b0, 1);        // 8
    k_gemm<<<gemm_blocks, 256>>>(x, W1, 1);       // 9
    k_agg <<<agg_blocks, 256>>>(1, b1, 1);        // 10
    k_gemm<<<gemm_blocks, 256>>>(x, W2, 2);       // 11
    k_agg <<<agg_blocks, 256>>>(0, b2, 0);        // 12

    dim3 pg(SPLITS, GG);
    k_pool<<<pg, 128>>>();                        // 13
    k_head<<<1, 512>>>(Wh, bh, out);              // 14
}